// round 9
// baseline (speedup 1.0000x reference)
#include <cuda_runtime.h>

// LSTM seq2seq: B=64, T=512, F=64, H=512, FUT=96 — persistent v4.
//  - 2 rows per thread (128 thr/block), weights in smem, c-state in registers.
//  - float4 staging (LDG.128/STS.128), double-buffered, 1 sync per 64-k chunk.
//  - v4: flag-tree grid barrier (release/acquire, no atomic contention),
//        skip final barriers, profile-aligned launch order (enc = index 5).

#define BB 64
#define TT 512
#define FF 64
#define HH 512
#define FUT 96
#define BH (BB*HH)          // 32768

#define NBLK 128
#define NTHR 128
#define WSS   514           // padded k-stride (ulonglong2) for K=512 tiles
#define WSS64 66            // padded k-stride for K=64 tiles
#define HSP 68              // padded floats per staged activation row (17 float4)
#define HSBUFF (64*HSP)     // one staging buffer (floats)

// ---------------- device scratch ----------------
__device__ float  g_y0[TT*BB*HH];
__device__ float  g_h1hist[FUT*BB*HH];
__device__ float  g_zero[BH];
__device__ float  g_c0[BH], g_c1[BH];
__device__ float  g_h1A[BH], g_h1B[BH], g_h0A[BH], g_h0B[BH];

__device__ float4 g_pW_enc_ih0[HH*FF];
__device__ float4 g_pW_enc_hh0[HH*HH];
__device__ float4 g_pW_enc_ih1[HH*HH];
__device__ float4 g_pW_enc_hh1[HH*HH];
__device__ float4 g_pW_dec_ih0[HH*FF];
__device__ float4 g_pW_dec_hh0[HH*HH];
__device__ float4 g_pW_dec_ih1[HH*HH];
__device__ float4 g_pW_dec_hh1[HH*HH];
__device__ float4 g_pW_dec0c[HH*HH];
__device__ float4 g_pb_enc0[HH], g_pb_enc1[HH], g_pb_dec0[HH], g_pb_dec1[HH], g_pb_dec0c[HH];

__device__ unsigned g_bgen;
__device__ unsigned g_flag[NBLK*8];   // padded arrival flags (32B stride)

// ---------------- f32x2 helpers ----------------
__device__ __forceinline__ unsigned long long bcast2(float v) {
    unsigned int u = __float_as_uint(v);
    unsigned long long r;
    asm("mov.b64 %0, {%1, %1};" : "=l"(r) : "r"(u));
    return r;
}
__device__ __forceinline__ unsigned long long pack2(float a, float b) {
    unsigned long long r;
    asm("mov.b64 %0, {%1, %2};" : "=l"(r) : "r"(__float_as_uint(a)), "r"(__float_as_uint(b)));
    return r;
}
__device__ __forceinline__ float2 unpack2(unsigned long long v) {
    unsigned int lo, hi;
    asm("mov.b64 {%0, %1}, %2;" : "=r"(lo), "=r"(hi) : "l"(v));
    return make_float2(__uint_as_float(lo), __uint_as_float(hi));
}
__device__ __forceinline__ void ffma2(unsigned long long& d, unsigned long long a, unsigned long long b) {
    asm("fma.rn.f32x2 %0, %1, %2, %0;" : "+l"(d) : "l"(a), "l"(b));
}
__device__ __forceinline__ void fadd2(unsigned long long& d, unsigned long long a) {
    asm("add.rn.f32x2 %0, %0, %1;" : "+l"(d) : "l"(a));
}
__device__ __forceinline__ ulonglong2 merge2(ulonglong2 p, ulonglong2 q) {
    fadd2(p.x, q.x); fadd2(p.y, q.y); return p;
}

// ---------------- flag-tree grid barrier ----------------
// Arrival: each block release-stores its flag (parallel, distinct L2 lines).
// Block 0: thread t polls block t's flag; after CTA sync, thread 0 releases g_bgen.
// Others: thread 0 acquires g_bgen, then CTA sync.
__device__ __forceinline__ void grid_barrier(unsigned gen) {
    __syncthreads();
    int tid = threadIdx.x;
    if (blockIdx.x == 0) {
        if (tid > 0) {   // tid t monitors block t (NTHR == NBLK)
            unsigned v;
            do {
                asm volatile("ld.acquire.gpu.u32 %0, [%1];" : "=r"(v) : "l"(&g_flag[tid * 8]));
            } while (v < gen);
        }
        __syncthreads();
        if (tid == 0) {
            asm volatile("st.release.gpu.u32 [%0], %1;" :: "l"(&g_bgen), "r"(gen));
        }
    } else {
        if (tid == 0) {
            asm volatile("st.release.gpu.u32 [%0], %1;" :: "l"(&g_flag[blockIdx.x * 8]), "r"(gen));
            unsigned v;
            do {
                asm volatile("ld.acquire.gpu.u32 %0, [%1];" : "=r"(v) : "l"(&g_bgen));
            } while (v < gen);
        }
        __syncthreads();
    }
}

// ---------------- chunk compute (64 k), 2 rows per thread ----------------
__device__ __forceinline__ void chunk_single(
    ulonglong2& p0, ulonglong2& q0, ulonglong2& p1, ulonglong2& q1,
    const ulonglong2* __restrict__ w,
    const float* __restrict__ h0, const float* __restrict__ h1)
{
#pragma unroll
    for (int kk = 0; kk < 64; kk += 4) {
        float4 a = *(const float4*)(h0 + kk);
        float4 b = *(const float4*)(h1 + kk);
        ulonglong2 w0 = w[kk], w1 = w[kk + 1], w2 = w[kk + 2], w3 = w[kk + 3];
        unsigned long long ax = bcast2(a.x), ay = bcast2(a.y), az = bcast2(a.z), aw = bcast2(a.w);
        unsigned long long bx = bcast2(b.x), by = bcast2(b.y), bz = bcast2(b.z), bw = bcast2(b.w);
        ffma2(p0.x, ax, w0.x); ffma2(p0.y, ax, w0.y);
        ffma2(p1.x, bx, w0.x); ffma2(p1.y, bx, w0.y);
        ffma2(q0.x, ay, w1.x); ffma2(q0.y, ay, w1.y);
        ffma2(q1.x, by, w1.x); ffma2(q1.y, by, w1.y);
        ffma2(p0.x, az, w2.x); ffma2(p0.y, az, w2.y);
        ffma2(p1.x, bz, w2.x); ffma2(p1.y, bz, w2.y);
        ffma2(q0.x, aw, w3.x); ffma2(q0.y, aw, w3.y);
        ffma2(q1.x, bw, w3.x); ffma2(q1.y, bw, w3.y);
    }
}

__device__ __forceinline__ void chunk_dual(
    ulonglong2& a0, ulonglong2& a1, ulonglong2& b0, ulonglong2& b1,
    const ulonglong2* __restrict__ wa, const ulonglong2* __restrict__ wb,
    const float* __restrict__ h0, const float* __restrict__ h1)
{
#pragma unroll
    for (int kk = 0; kk < 64; kk += 2) {
        float2 a = *(const float2*)(h0 + kk);
        float2 b = *(const float2*)(h1 + kk);
        ulonglong2 wa0 = wa[kk], wa1 = wa[kk + 1];
        ulonglong2 wb0 = wb[kk], wb1 = wb[kk + 1];
        unsigned long long ax = bcast2(a.x), ay = bcast2(a.y);
        unsigned long long bx = bcast2(b.x), by = bcast2(b.y);
        ffma2(a0.x, ax, wa0.x); ffma2(a0.y, ax, wa0.y);
        ffma2(a1.x, bx, wa0.x); ffma2(a1.y, bx, wa0.y);
        ffma2(b0.x, ax, wb0.x); ffma2(b0.y, ax, wb0.y);
        ffma2(b1.x, bx, wb0.x); ffma2(b1.y, bx, wb0.y);
        ffma2(a0.x, ay, wa1.x); ffma2(a0.y, ay, wa1.y);
        ffma2(a1.x, by, wa1.x); ffma2(a1.y, by, wa1.y);
        ffma2(b0.x, ay, wb1.x); ffma2(b0.y, ay, wb1.y);
        ffma2(b1.x, by, wb1.x); ffma2(b1.y, by, wb1.y);
    }
}

// ---------------- staged K=512 phases ----------------
__device__ __forceinline__ void phase512_single(
    ulonglong2& p0, ulonglong2& q0, ulonglong2& p1, ulonglong2& q1,
    const float* __restrict__ x, const ulonglong2* __restrict__ W,
    float* hs, int tid, int jl, int rh)
{
    const float4* x4 = (const float4*)x;
    int rbase = tid >> 4, c4 = tid & 15;
    float4 pf[8];
#pragma unroll
    for (int u = 0; u < 8; u++) pf[u] = x4[(rbase + u * 8) * 128 + c4];
#pragma unroll 1
    for (int kc = 0; kc < HH; kc += 64) {
        float* buf = hs + ((kc >> 6) & 1) * HSBUFF;
        float4* buf4 = (float4*)buf;
#pragma unroll
        for (int u = 0; u < 8; u++) buf4[(rbase + u * 8) * 17 + c4] = pf[u];
        __syncthreads();
        if (kc + 64 < HH) {
            int k4 = (kc + 64) >> 2;
#pragma unroll
            for (int u = 0; u < 8; u++) pf[u] = x4[(rbase + u * 8) * 128 + k4 + c4];
        }
        chunk_single(p0, q0, p1, q1, W + jl * WSS + kc,
                     buf + rh * HSP, buf + (rh + 32) * HSP);
    }
}

__device__ __forceinline__ void phase512_dual(
    ulonglong2& a0, ulonglong2& a1, ulonglong2& b0, ulonglong2& b1,
    const float* __restrict__ x,
    const ulonglong2* __restrict__ Wa, const ulonglong2* __restrict__ Wb,
    float* hs, int tid, int jl, int rh)
{
    const float4* x4 = (const float4*)x;
    int rbase = tid >> 4, c4 = tid & 15;
    float4 pf[8];
#pragma unroll
    for (int u = 0; u < 8; u++) pf[u] = x4[(rbase + u * 8) * 128 + c4];
#pragma unroll 1
    for (int kc = 0; kc < HH; kc += 64) {
        float* buf = hs + ((kc >> 6) & 1) * HSBUFF;
        float4* buf4 = (float4*)buf;
#pragma unroll
        for (int u = 0; u < 8; u++) buf4[(rbase + u * 8) * 17 + c4] = pf[u];
        __syncthreads();
        if (kc + 64 < HH) {
            int k4 = (kc + 64) >> 2;
#pragma unroll
            for (int u = 0; u < 8; u++) pf[u] = x4[(rbase + u * 8) * 128 + k4 + c4];
        }
        chunk_dual(a0, a1, b0, b1, Wa + jl * WSS + kc, Wb + jl * WSS + kc,
                   buf + rh * HSP, buf + (rh + 32) * HSP);
    }
}

__device__ __forceinline__ void phase64_single(
    ulonglong2& p0, ulonglong2& q0, ulonglong2& p1, ulonglong2& q1,
    const float* __restrict__ x, long xstride,
    const ulonglong2* __restrict__ W, float* hs, int tid, int jl, int rh)
{
    const float4* x4 = (const float4*)x;
    long xs4 = xstride >> 2;
    int rbase = tid >> 4, c4 = tid & 15;
    float* buf = hs + HSBUFF;   // buffer 1 (parity-safe vs phase512 start)
    float4* buf4 = (float4*)buf;
#pragma unroll
    for (int u = 0; u < 8; u++)
        buf4[(rbase + u * 8) * 17 + c4] = x4[(long)(rbase + u * 8) * xs4 + c4];
    __syncthreads();
    chunk_single(p0, q0, p1, q1, W + jl * WSS64,
                 buf + rh * HSP, buf + (rh + 32) * HSP);
}

__device__ __forceinline__ float cellfin(ulonglong2 acc, float& c) {
    float2 vif = unpack2(acc.x);
    float2 vgo = unpack2(acc.y);
    float si = 1.f / (1.f + __expf(-vif.x));
    float sf = 1.f / (1.f + __expf(-vif.y));
    float so = 1.f / (1.f + __expf(-vgo.y));
    float cn = sf * c + si * tanhf(vgo.x);
    c = cn;
    return so * tanhf(cn);
}

#define ENC_SMEM ((3*4*WSS + 4*WSS64) * 16 + 2*HSBUFF*4)
#define DEC_SMEM ((4*4*WSS + 4*WSS64) * 16 + 2*HSBUFF*4)

// ---------------- persistent encoder: L0 + L1 software-pipelined ----------------
__global__ void __launch_bounds__(NTHR, 1) enc_kernel(
    const float* __restrict__ in_seq,
    const float4* __restrict__ pW0x, const float4* __restrict__ pW0h,
    const float4* __restrict__ pW1x, const float4* __restrict__ pW1h,
    const float4* __restrict__ pb0, const float4* __restrict__ pb1,
    const float* __restrict__ zerobuf,
    float* __restrict__ y0, float* __restrict__ h1A, float* __restrict__ h1B,
    float* __restrict__ c0out, float* __restrict__ c1out)
{
    extern __shared__ __align__(16) unsigned char smraw[];
    ulonglong2* W0h = (ulonglong2*)smraw;
    ulonglong2* W1x = W0h + 4 * WSS;
    ulonglong2* W1h = W1x + 4 * WSS;
    ulonglong2* W0x = W1h + 4 * WSS;
    float* hs = (float*)(W0x + 4 * WSS64);

    int tid = threadIdx.x, jl = tid & 3, rh = tid >> 2;   // rh 0..31
    int j0 = blockIdx.x * 4, j = j0 + jl;
    int idx0 = (rh << 9) + j;
    int idx1 = ((rh + 32) << 9) + j;

    {   // load weight tiles (once)
        const ulonglong2* g0h = (const ulonglong2*)pW0h + (size_t)j0 * HH;
        const ulonglong2* g1x = (const ulonglong2*)pW1x + (size_t)j0 * HH;
        const ulonglong2* g1h = (const ulonglong2*)pW1h + (size_t)j0 * HH;
#pragma unroll 2
        for (int i = tid; i < 4 * HH; i += NTHR) {
            int jj = i >> 9, kk = i & 511;
            W0h[jj * WSS + kk] = g0h[i];
            W1x[jj * WSS + kk] = g1x[i];
            W1h[jj * WSS + kk] = g1h[i];
        }
        const ulonglong2* g0x = (const ulonglong2*)pW0x + (size_t)j0 * FF;
#pragma unroll
        for (int i = tid; i < 4 * FF; i += NTHR) {
            int jj = i >> 6, kk = i & 63;
            W0x[jj * WSS64 + kk] = g0x[i];
        }
    }
    float4 b0 = pb0[j], b1 = pb1[j];
    unsigned long long b0x = pack2(b0.x, b0.y), b0y = pack2(b0.z, b0.w);
    unsigned long long b1x = pack2(b1.x, b1.y), b1y = pack2(b1.z, b1.w);
    float c0a = 0.f, c0b = 0.f, c1a = 0.f, c1b = 0.f;
    __syncthreads();

    unsigned gen = 0;
    for (int slot = 0; slot <= TT; slot++) {
        bool doL0 = (slot < TT);
        bool doL1 = (slot > 0);
        const float* yprev = (slot == 0) ? zerobuf : (y0 + (size_t)(slot - 1) * BH);

        ulonglong2 P00, Q00, P01, Q01, P10, Q10, P11, Q11;
        Q00.x = Q00.y = Q01.x = Q01.y = 0ULL;
        Q10.x = Q10.y = Q11.x = Q11.y = 0ULL;
        P00.x = b0x; P00.y = b0y; P01.x = b0x; P01.y = b0y;
        P10.x = b1x; P10.y = b1y; P11.x = b1x; P11.y = b1y;

        if (doL0)
            phase64_single(P00, Q00, P01, Q01, in_seq + (size_t)slot * FF,
                           (long)TT * FF, W0x, hs, tid, jl, rh);

        if (doL0 && doL1)
            phase512_dual(P00, P01, P10, P11, yprev, W0h, W1x, hs, tid, jl, rh);
        else if (doL0)
            phase512_single(P00, Q00, P01, Q01, yprev, W0h, hs, tid, jl, rh);
        else
            phase512_single(P10, Q10, P11, Q11, yprev, W1x, hs, tid, jl, rh);

        if (doL1) {
            const float* h1p = (slot == 1) ? zerobuf : ((slot & 1) ? h1A : h1B);
            phase512_single(P10, Q10, P11, Q11, h1p, W1h, hs, tid, jl, rh);
            float* h1o = (slot & 1) ? h1B : h1A;
            h1o[idx0] = cellfin(merge2(P10, Q10), c1a);
            h1o[idx1] = cellfin(merge2(P11, Q11), c1b);
        }
        if (doL0) {
            float* yo = y0 + (size_t)slot * BH;
            yo[idx0] = cellfin(merge2(P00, Q00), c0a);
            yo[idx1] = cellfin(merge2(P01, Q01), c0b);
        }

        if (slot < TT) {     // last slot: kernel boundary orders everything
            gen++;
            grid_barrier(gen);
        }
    }
    c0out[idx0] = c0a; c0out[idx1] = c0b;
    c1out[idx0] = c1a; c1out[idx1] = c1b;
    // final h1 at slot TT (even) -> h1A
}

// ---------------- persistent decoder ----------------
__global__ void __launch_bounds__(NTHR, 1) dec_kernel(
    const float* __restrict__ in_seq,
    const float4* __restrict__ pWd0x, const float4* __restrict__ pWd0c,
    const float4* __restrict__ pWdh0, const float4* __restrict__ pWdx1,
    const float4* __restrict__ pWdh1,
    const float4* __restrict__ pbD0, const float4* __restrict__ pbD0c,
    const float4* __restrict__ pbD1,
    const float* __restrict__ h0init, const float* __restrict__ h1init,
    const float* __restrict__ c0in, const float* __restrict__ c1in,
    float* __restrict__ h0A, float* __restrict__ h0B, float* __restrict__ h1hist)
{
    extern __shared__ __align__(16) unsigned char smraw[];
    ulonglong2* Wc  = (ulonglong2*)smraw;
    ulonglong2* Wh0 = Wc  + 4 * WSS;
    ulonglong2* Wx1 = Wh0 + 4 * WSS;
    ulonglong2* Wh1 = Wx1 + 4 * WSS;
    ulonglong2* W0x = Wh1 + 4 * WSS;
    float* hs = (float*)(W0x + 4 * WSS64);

    int tid = threadIdx.x, jl = tid & 3, rh = tid >> 2;
    int j0 = blockIdx.x * 4, j = j0 + jl;
    int idx0 = (rh << 9) + j;
    int idx1 = ((rh + 32) << 9) + j;

    {
        const ulonglong2* gc  = (const ulonglong2*)pWd0c + (size_t)j0 * HH;
        const ulonglong2* gh0 = (const ulonglong2*)pWdh0 + (size_t)j0 * HH;
        const ulonglong2* gx1 = (const ulonglong2*)pWdx1 + (size_t)j0 * HH;
        const ulonglong2* gh1 = (const ulonglong2*)pWdh1 + (size_t)j0 * HH;
#pragma unroll 2
        for (int i = tid; i < 4 * HH; i += NTHR) {
            int jj = i >> 9, kk = i & 511;
            Wc[jj * WSS + kk]  = gc[i];
            Wh0[jj * WSS + kk] = gh0[i];
            Wx1[jj * WSS + kk] = gx1[i];
            Wh1[jj * WSS + kk] = gh1[i];
        }
        const ulonglong2* g0x = (const ulonglong2*)pWd0x + (size_t)j0 * FF;
#pragma unroll
        for (int i = tid; i < 4 * FF; i += NTHR) {
            int jj = i >> 6, kk = i & 63;
            W0x[jj * WSS64 + kk] = g0x[i];
        }
    }
    float4 bd0 = pbD0[j], bd0c = pbD0c[j], bd1 = pbD1[j];
    float c0a = c0in[idx0], c0b = c0in[idx1];
    float c1a = c1in[idx0], c1b = c1in[idx1];
    __syncthreads();

    unsigned gen = 0;
    const float* h0prev = h0init;
    const float* h1prev = h1init;

    for (int t = 0; t < FUT; t++) {
        // ---- cell d0 ----
        ulonglong2 P0, Q0, P1, Q1;
        Q0.x = Q0.y = Q1.x = Q1.y = 0ULL;
        if (t == 0) {
            P0.x = pack2(bd0.x, bd0.y); P0.y = pack2(bd0.z, bd0.w);
            P1 = P0;
            phase64_single(P0, Q0, P1, Q1, in_seq + (size_t)(TT - 1) * FF,
                           (long)TT * FF, W0x, hs, tid, jl, rh);
        } else {
            P0.x = pack2(bd0c.x, bd0c.y); P0.y = pack2(bd0c.z, bd0c.w);
            P1 = P0;
            phase512_single(P0, Q0, P1, Q1, h1hist + (size_t)(t - 1) * BH, Wc,
                            hs, tid, jl, rh);
        }
        phase512_single(P0, Q0, P1, Q1, h0prev, Wh0, hs, tid, jl, rh);
        float* h0out = (t & 1) ? h0B : h0A;
        h0out[idx0] = cellfin(merge2(P0, Q0), c0a);
        h0out[idx1] = cellfin(merge2(P1, Q1), c0b);
        gen++; grid_barrier(gen);

        // ---- cell d1 ----
        ulonglong2 R0, S0, R1, S1;
        S0.x = S0.y = S1.x = S1.y = 0ULL;
        R0.x = pack2(bd1.x, bd1.y); R0.y = pack2(bd1.z, bd1.w);
        R1 = R0;
        phase512_single(R0, S0, R1, S1, h0out, Wx1, hs, tid, jl, rh);
        phase512_single(R0, S0, R1, S1, h1prev, Wh1, hs, tid, jl, rh);
        float* h1o = h1hist + (size_t)t * BH;
        h1o[idx0] = cellfin(merge2(R0, S0), c1a);
        h1o[idx1] = cellfin(merge2(R1, S1), c1b);
        if (t < FUT - 1) {   // final barrier unnecessary (kernel boundary)
            gen++; grid_barrier(gen);
        }
        h0prev = h0out;
        h1prev = h1o;
    }
}

// ---------------- setup kernels ----------------
__global__ void pack_all_kernel(
    const float* __restrict__ s0, const float* __restrict__ s1,
    const float* __restrict__ s2, const float* __restrict__ s3,
    const float* __restrict__ s4, const float* __restrict__ s5,
    const float* __restrict__ s6, const float* __restrict__ s7,
    float4* __restrict__ d0, float4* __restrict__ d1,
    float4* __restrict__ d2, float4* __restrict__ d3,
    float4* __restrict__ d4, float4* __restrict__ d5,
    float4* __restrict__ d6, float4* __restrict__ d7,
    const float* __restrict__ bi0, const float* __restrict__ bh0,
    const float* __restrict__ bi1, const float* __restrict__ bh1,
    const float* __restrict__ bi2, const float* __restrict__ bh2,
    const float* __restrict__ bi3, const float* __restrict__ bh3,
    float4* __restrict__ pb0, float4* __restrict__ pb1,
    float4* __restrict__ pb2, float4* __restrict__ pb3)
{
    int m = blockIdx.y;
    int idx = blockIdx.x * 256 + threadIdx.x;
    if (m < 8) {
        const float* S; float4* D; int Kin;
        switch (m) {
            case 0: S = s0; D = d0; Kin = FF; break;
            case 1: S = s1; D = d1; Kin = HH; break;
            case 2: S = s2; D = d2; Kin = HH; break;
            case 3: S = s3; D = d3; Kin = HH; break;
            case 4: S = s4; D = d4; Kin = FF; break;
            case 5: S = s5; D = d5; Kin = HH; break;
            case 6: S = s6; D = d6; Kin = HH; break;
            default: S = s7; D = d7; Kin = HH; break;
        }
        if (idx >= HH * Kin) return;
        int jj = idx / Kin, k = idx - jj * Kin;
        D[idx] = make_float4(S[jj * Kin + k], S[(jj + 512) * Kin + k],
                             S[(jj + 1024) * Kin + k], S[(jj + 1536) * Kin + k]);
    } else {
        if (idx >= 4 * HH) return;
        int which = idx >> 9, jj = idx & 511;
        const float* A; const float* Bb; float4* P;
        switch (which) {
            case 0: A = bi0; Bb = bh0; P = pb0; break;
            case 1: A = bi1; Bb = bh1; P = pb1; break;
            case 2: A = bi2; Bb = bh2; P = pb2; break;
            default: A = bi3; Bb = bh3; P = pb3; break;
        }
        P[jj] = make_float4(A[jj] + Bb[jj], A[jj + 512] + Bb[jj + 512],
                            A[jj + 1024] + Bb[jj + 1024], A[jj + 1536] + Bb[jj + 1536]);
    }
}

__global__ void combine_dec0_kernel(const float4* __restrict__ pWih0, const float* __restrict__ fcW,
                                    const float4* __restrict__ pb0, const float* __restrict__ fcb,
                                    float4* __restrict__ Pc, float4* __restrict__ pbc) {
    int idx = blockIdx.x * 256 + threadIdx.x;
    if (idx >= HH * HH) return;
    int jj = idx >> 9, hh = idx & 511;
    float4 acc = make_float4(0.f, 0.f, 0.f, 0.f);
#pragma unroll 8
    for (int n = 0; n < FF; n++) {
        float4 w = pWih0[(jj << 6) + n];
        float f = fcW[(n << 9) + hh];
        acc.x += w.x * f; acc.y += w.y * f; acc.z += w.z * f; acc.w += w.w * f;
    }
    Pc[idx] = acc;
    if (hh == 0) {
        float4 bb = pb0[jj];
#pragma unroll 8
        for (int n = 0; n < FF; n++) {
            float4 w = pWih0[(jj << 6) + n];
            float f = fcb[n];
            bb.x += w.x * f; bb.y += w.y * f; bb.z += w.z * f; bb.w += w.w * f;
        }
        pbc[jj] = bb;
    }
}
__global__ void init_kernel(float* zerobuf) {
    int i = blockIdx.x * 256 + threadIdx.x;
    if (i < BH) zerobuf[i] = 0.f;
    if (i < NBLK * 8) g_flag[i] = 0;
    if (i == 0) g_bgen = 0;
}
__global__ void nop_kernel() {}
__global__ void reset_bar_kernel() {
    int i = threadIdx.x;
    if (i < NBLK * 8) g_flag[i] = 0;
    if (i == 0) g_bgen = 0;
}

__global__ void final_fc_kernel(const float* __restrict__ h1hist, const float* __restrict__ fcW,
                                const float* __restrict__ fcb, float* __restrict__ out) {
    int t = blockIdx.y;
    int l = blockIdx.x * 256 + threadIdx.x;
    int b = l >> 6, n = l & 63;
    const float4* h4 = (const float4*)(h1hist + ((size_t)t * BB + b) * HH);
    const float4* w4 = (const float4*)(fcW + (size_t)n * HH);
    float acc = fcb[n];
#pragma unroll 8
    for (int k = 0; k < HH / 4; k++) {
        float4 a = h4[k], w = w4[k];
        acc += a.x * w.x + a.y * w.y + a.z * w.z + a.w * w.w;
    }
    out[((size_t)b * FUT + t) * FF + n] = acc;
}

// ---------------- host ----------------
extern "C" void kernel_launch(void* const* d_in, const int* in_sizes, int n_in,
                              void* d_out, int out_size) {
    const float* in_seq = (const float*)d_in[0];
    const float* eWih0  = (const float*)d_in[1];
    const float* eWhh0  = (const float*)d_in[2];
    const float* ebih0  = (const float*)d_in[3];
    const float* ebhh0  = (const float*)d_in[4];
    const float* eWih1  = (const float*)d_in[5];
    const float* eWhh1  = (const float*)d_in[6];
    const float* ebih1  = (const float*)d_in[7];
    const float* ebhh1  = (const float*)d_in[8];
    const float* dWih0  = (const float*)d_in[9];
    const float* dWhh0  = (const float*)d_in[10];
    const float* dbih0  = (const float*)d_in[11];
    const float* dbhh0  = (const float*)d_in[12];
    const float* dWih1  = (const float*)d_in[13];
    const float* dWhh1  = (const float*)d_in[14];
    const float* dbih1  = (const float*)d_in[15];
    const float* dbhh1  = (const float*)d_in[16];
    const float* fcW    = (const float*)d_in[17];
    const float* fcb    = (const float*)d_in[18];
    float* out = (float*)d_out;

    static int s_attr_done = 0;
    if (!s_attr_done) {
        cudaFuncSetAttribute(enc_kernel, cudaFuncAttributeMaxDynamicSharedMemorySize, ENC_SMEM);
        cudaFuncSetAttribute(dec_kernel, cudaFuncAttributeMaxDynamicSharedMemorySize, DEC_SMEM);
        s_attr_done = 1;
    }

    float4 *pWeih0, *pWehh0, *pWeih1, *pWehh1, *pWdih0, *pWdhh0, *pWdih1, *pWdhh1, *pWd0c;
    float4 *pbE0, *pbE1, *pbD0, *pbD1, *pbD0c;
    float *y0, *h1hist, *zerobuf, *c0, *c1, *h1A, *h1B, *h0A, *h0B;
    cudaGetSymbolAddress((void**)&y0,      g_y0);
    cudaGetSymbolAddress((void**)&h1hist,  g_h1hist);
    cudaGetSymbolAddress((void**)&zerobuf, g_zero);
    cudaGetSymbolAddress((void**)&c0,      g_c0);
    cudaGetSymbolAddress((void**)&c1,      g_c1);
    cudaGetSymbolAddress((void**)&h1A,     g_h1A);
    cudaGetSymbolAddress((void**)&h1B,     g_h1B);
    cudaGetSymbolAddress((void**)&h0A,     g_h0A);
    cudaGetSymbolAddress((void**)&h0B,     g_h0B);
    cudaGetSymbolAddress((void**)&pWeih0,  g_pW_enc_ih0);
    cudaGetSymbolAddress((void**)&pWehh0,  g_pW_enc_hh0);
    cudaGetSymbolAddress((void**)&pWeih1,  g_pW_enc_ih1);
    cudaGetSymbolAddress((void**)&pWehh1,  g_pW_enc_hh1);
    cudaGetSymbolAddress((void**)&pWdih0,  g_pW_dec_ih0);
    cudaGetSymbolAddress((void**)&pWdhh0,  g_pW_dec_hh0);
    cudaGetSymbolAddress((void**)&pWdih1,  g_pW_dec_ih1);
    cudaGetSymbolAddress((void**)&pWdhh1,  g_pW_dec_hh1);
    cudaGetSymbolAddress((void**)&pWd0c,   g_pW_dec0c);
    cudaGetSymbolAddress((void**)&pbE0,    g_pb_enc0);
    cudaGetSymbolAddress((void**)&pbE1,    g_pb_enc1);
    cudaGetSymbolAddress((void**)&pbD0,    g_pb_dec0);
    cudaGetSymbolAddress((void**)&pbD1,    g_pb_dec1);
    cudaGetSymbolAddress((void**)&pbD0c,   g_pb_dec0c);

    // Launch order: harness pre-launch(≈1) + [pack, combine, init, nop, enc,...]
    // puts enc_kernel at overall launch index 5 for ncu (-s 5 -c 1).
    {
        dim3 grid(1024, 9);
        pack_all_kernel<<<grid, 256>>>(
            eWih0, eWhh0, eWih1, eWhh1, dWih0, dWhh0, dWih1, dWhh1,
            pWeih0, pWehh0, pWeih1, pWehh1, pWdih0, pWdhh0, pWdih1, pWdhh1,
            ebih0, ebhh0, ebih1, ebhh1, dbih0, dbhh0, dbih1, dbhh1,
            pbE0, pbE1, pbD0, pbD1);
    }
    combine_dec0_kernel<<<(HH * HH + 255) / 256, 256>>>(pWdih0, fcW, pbD0, fcb, pWd0c, pbD0c);
    init_kernel<<<(BH + 255) / 256, 256>>>(zerobuf);
    nop_kernel<<<1, 1>>>();

    enc_kernel<<<NBLK, NTHR, ENC_SMEM>>>(
        in_seq, pWeih0, pWehh0, pWeih1, pWehh1, pbE0, pbE1,
        zerobuf, y0, h1A, h1B, c0, c1);

    reset_bar_kernel<<<1, 1024>>>();

    dec_kernel<<<NBLK, NTHR, DEC_SMEM>>>(
        in_seq, pWdih0, pWd0c, pWdhh0, pWdih1, pWdhh1,
        pbD0, pbD0c, pbD1,
        y0 + (size_t)(TT - 1) * BH,
        h1A,
        c0, c1, h0A, h0B, h1hist);

    {
        dim3 grid(16, FUT);
        final_fc_kernel<<<grid, 256>>>(h1hist, fcW, fcb, out);
    }
}

// round 10
// speedup vs baseline: 1.0011x; 1.0011x over previous
#include <cuda_runtime.h>

// LSTM seq2seq: B=64, T=512, F=64, H=512, FUT=96 — persistent v5.
//  - k-pair f32x2 lanes: weights packed as per-gate (k,k+1) 64-bit pairs, so the
//    FFMA2 activation operand comes straight from LDS (NO broadcast MOVs).
//  - 2 rows per thread, 128 thr/block, weights in smem, c in registers.
//  - float4 staging, double-buffered, 1 sync per 64-k chunk; flag-tree barrier.

#define BB 64
#define TT 512
#define FF 64
#define HH 512
#define FUT 96
#define BH (BB*HH)          // 32768

#define NBLK 128
#define NTHR 128
#define WSS   514           // padded per-j row stride (ulonglong2 units) K=512
#define WSS64 66            // padded row stride for K=64
#define HSP 68              // padded floats per staged activation row
#define HSBUFF (64*HSP)

typedef unsigned long long u64;

// ---------------- device scratch ----------------
__device__ float  g_y0[TT*BB*HH];
__device__ float  g_h1hist[FUT*BB*HH];
__device__ float  g_zero[BH];
__device__ float  g_c0[BH], g_c1[BH];
__device__ float  g_h1A[BH], g_h1B[BH], g_h0A[BH], g_h0B[BH];

// pair-packed weights: entry (j,k2) = 2 float4: {i(k),i(k+1),f(k),f(k+1)} and {g.., o..}
__device__ float4 g_pW_enc_ih0[HH*FF];
__device__ float4 g_pW_enc_hh0[HH*HH];
__device__ float4 g_pW_enc_ih1[HH*HH];
__device__ float4 g_pW_enc_hh1[HH*HH];
__device__ float4 g_pW_dec_ih0[HH*FF];
__device__ float4 g_pW_dec_hh0[HH*HH];
__device__ float4 g_pW_dec_ih1[HH*HH];
__device__ float4 g_pW_dec_hh1[HH*HH];
__device__ float4 g_pW_dec0c[HH*HH];
__device__ float4 g_pb_enc0[HH], g_pb_enc1[HH], g_pb_dec0[HH], g_pb_dec1[HH], g_pb_dec0c[HH];

__device__ unsigned g_bgen;
__device__ unsigned g_flag[NBLK*8];

// ---------------- f32x2 helpers ----------------
__device__ __forceinline__ u64 pack2(float a, float b) {
    u64 r;
    asm("mov.b64 %0, {%1, %2};" : "=l"(r) : "r"(__float_as_uint(a)), "r"(__float_as_uint(b)));
    return r;
}
__device__ __forceinline__ float2 unpack2(u64 v) {
    unsigned int lo, hi;
    asm("mov.b64 {%0, %1}, %2;" : "=r"(lo), "=r"(hi) : "l"(v));
    return make_float2(__uint_as_float(lo), __uint_as_float(hi));
}
__device__ __forceinline__ void ffma2(u64& d, u64 a, u64 b) {
    asm("fma.rn.f32x2 %0, %1, %2, %0;" : "+l"(d) : "l"(a), "l"(b));
}

// ---------------- flag-tree grid barrier ----------------
__device__ __forceinline__ void grid_barrier(unsigned gen) {
    __syncthreads();
    int tid = threadIdx.x;
    if (blockIdx.x == 0) {
        if (tid > 0) {
            unsigned v;
            do {
                asm volatile("ld.acquire.gpu.u32 %0, [%1];" : "=r"(v) : "l"(&g_flag[tid * 8]));
            } while (v < gen);
        }
        __syncthreads();
        if (tid == 0) {
            asm volatile("st.release.gpu.u32 [%0], %1;" :: "l"(&g_bgen), "r"(gen));
        }
    } else {
        if (tid == 0) {
            asm volatile("st.release.gpu.u32 [%0], %1;" :: "l"(&g_flag[blockIdx.x * 8]), "r"(gen));
            unsigned v;
            do {
                asm volatile("ld.acquire.gpu.u32 %0, [%1];" : "=r"(v) : "l"(&g_bgen));
            } while (v < gen);
        }
        __syncthreads();
    }
}

// ---------------- chunk compute over 64 k, 2 rows per thread ----------------
// A[0..3] = row0 gates i,f,g,o (each u64 = 2 k-lanes); A[4..7] = row1.
// w: 2 ulonglong2 per k-pair: [2*k2]={wi2,wf2}, [2*k2+1]={wg2,wo2}.
__device__ __forceinline__ void chunk16(
    u64* __restrict__ A,
    const ulonglong2* __restrict__ w,
    const float* __restrict__ h0, const float* __restrict__ h1)
{
#pragma unroll
    for (int k2 = 0; k2 < 32; k2 += 2) {
        ulonglong2 a = *(const ulonglong2*)(h0 + k2 * 2);   // (k..k+1),(k+2..k+3)
        ulonglong2 b = *(const ulonglong2*)(h1 + k2 * 2);
        ulonglong2 wif0 = w[2 * k2 + 0];
        ulonglong2 wgo0 = w[2 * k2 + 1];
        ulonglong2 wif1 = w[2 * k2 + 2];
        ulonglong2 wgo1 = w[2 * k2 + 3];
        ffma2(A[0], a.x, wif0.x); ffma2(A[1], a.x, wif0.y);
        ffma2(A[2], a.x, wgo0.x); ffma2(A[3], a.x, wgo0.y);
        ffma2(A[4], b.x, wif0.x); ffma2(A[5], b.x, wif0.y);
        ffma2(A[6], b.x, wgo0.x); ffma2(A[7], b.x, wgo0.y);
        ffma2(A[0], a.y, wif1.x); ffma2(A[1], a.y, wif1.y);
        ffma2(A[2], a.y, wgo1.x); ffma2(A[3], a.y, wgo1.y);
        ffma2(A[4], b.y, wif1.x); ffma2(A[5], b.y, wif1.y);
        ffma2(A[6], b.y, wgo1.x); ffma2(A[7], b.y, wgo1.y);
    }
}

// Dual matrices sharing the same activations.
__device__ __forceinline__ void chunk16_dual(
    u64* __restrict__ A, u64* __restrict__ B,
    const ulonglong2* __restrict__ wa, const ulonglong2* __restrict__ wb,
    const float* __restrict__ h0, const float* __restrict__ h1)
{
#pragma unroll
    for (int k2 = 0; k2 < 32; k2++) {
        u64 a = *(const u64*)(h0 + k2 * 2);
        u64 b = *(const u64*)(h1 + k2 * 2);
        ulonglong2 waif = wa[2 * k2], wago = wa[2 * k2 + 1];
        ulonglong2 wbif = wb[2 * k2], wbgo = wb[2 * k2 + 1];
        ffma2(A[0], a, waif.x); ffma2(A[1], a, waif.y);
        ffma2(A[2], a, wago.x); ffma2(A[3], a, wago.y);
        ffma2(A[4], b, waif.x); ffma2(A[5], b, waif.y);
        ffma2(A[6], b, wago.x); ffma2(A[7], b, wago.y);
        ffma2(B[0], a, wbif.x); ffma2(B[1], a, wbif.y);
        ffma2(B[2], a, wbgo.x); ffma2(B[3], a, wbgo.y);
        ffma2(B[4], b, wbif.x); ffma2(B[5], b, wbif.y);
        ffma2(B[6], b, wbgo.x); ffma2(B[7], b, wbgo.y);
    }
}

// ---------------- staged phases ----------------
__device__ __forceinline__ void phase512_single(
    u64* __restrict__ A,
    const float* __restrict__ x, const ulonglong2* __restrict__ W,
    float* hs, int tid, int jl, int rh)
{
    const float4* x4 = (const float4*)x;
    int rbase = tid >> 4, c4 = tid & 15;
    float4 pf[8];
#pragma unroll
    for (int u = 0; u < 8; u++) pf[u] = x4[(rbase + u * 8) * 128 + c4];
#pragma unroll 1
    for (int kc = 0; kc < HH; kc += 64) {
        float* buf = hs + ((kc >> 6) & 1) * HSBUFF;
        float4* buf4 = (float4*)buf;
#pragma unroll
        for (int u = 0; u < 8; u++) buf4[(rbase + u * 8) * 17 + c4] = pf[u];
        __syncthreads();
        if (kc + 64 < HH) {
            int k4 = (kc + 64) >> 2;
#pragma unroll
            for (int u = 0; u < 8; u++) pf[u] = x4[(rbase + u * 8) * 128 + k4 + c4];
        }
        chunk16(A, W + jl * WSS + kc, buf + rh * HSP, buf + (rh + 32) * HSP);
    }
}

__device__ __forceinline__ void phase512_dual(
    u64* __restrict__ A, u64* __restrict__ B,
    const float* __restrict__ x,
    const ulonglong2* __restrict__ Wa, const ulonglong2* __restrict__ Wb,
    float* hs, int tid, int jl, int rh)
{
    const float4* x4 = (const float4*)x;
    int rbase = tid >> 4, c4 = tid & 15;
    float4 pf[8];
#pragma unroll
    for (int u = 0; u < 8; u++) pf[u] = x4[(rbase + u * 8) * 128 + c4];
#pragma unroll 1
    for (int kc = 0; kc < HH; kc += 64) {
        float* buf = hs + ((kc >> 6) & 1) * HSBUFF;
        float4* buf4 = (float4*)buf;
#pragma unroll
        for (int u = 0; u < 8; u++) buf4[(rbase + u * 8) * 17 + c4] = pf[u];
        __syncthreads();
        if (kc + 64 < HH) {
            int k4 = (kc + 64) >> 2;
#pragma unroll
            for (int u = 0; u < 8; u++) pf[u] = x4[(rbase + u * 8) * 128 + k4 + c4];
        }
        chunk16_dual(A, B, Wa + jl * WSS + kc, Wb + jl * WSS + kc,
                     buf + rh * HSP, buf + (rh + 32) * HSP);
    }
}

__device__ __forceinline__ void phase64_single(
    u64* __restrict__ A,
    const float* __restrict__ x, long xstride,
    const ulonglong2* __restrict__ W, float* hs, int tid, int jl, int rh)
{
    const float4* x4 = (const float4*)x;
    long xs4 = xstride >> 2;
    int rbase = tid >> 4, c4 = tid & 15;
    float* buf = hs + HSBUFF;   // buffer 1 (parity-safe vs phase512 start)
    float4* buf4 = (float4*)buf;
#pragma unroll
    for (int u = 0; u < 8; u++)
        buf4[(rbase + u * 8) * 17 + c4] = x4[(long)(rbase + u * 8) * xs4 + c4];
    __syncthreads();
    chunk16(A, W + jl * WSS64, buf + rh * HSP, buf + (rh + 32) * HSP);
}

__device__ __forceinline__ float cellfin4(u64 gi2, u64 gf2, u64 gg2, u64 go2, float& c) {
    float2 vi = unpack2(gi2), vf = unpack2(gf2), vg = unpack2(gg2), vo = unpack2(go2);
    float gi = vi.x + vi.y, gf = vf.x + vf.y, gg = vg.x + vg.y, go = vo.x + vo.y;
    float si = 1.f / (1.f + __expf(-gi));
    float sf = 1.f / (1.f + __expf(-gf));
    float so = 1.f / (1.f + __expf(-go));
    float cn = sf * c + si * tanhf(gg);
    c = cn;
    return so * tanhf(cn);
}

__device__ __forceinline__ void bias_init(u64* A, float4 b) {
    A[0] = pack2(b.x, 0.f); A[1] = pack2(b.y, 0.f);
    A[2] = pack2(b.z, 0.f); A[3] = pack2(b.w, 0.f);
    A[4] = A[0]; A[5] = A[1]; A[6] = A[2]; A[7] = A[3];
}

#define ENC_SMEM ((3*4*WSS + 4*WSS64) * 16 + 2*HSBUFF*4)
#define DEC_SMEM ((4*4*WSS + 4*WSS64) * 16 + 2*HSBUFF*4)

// ---------------- persistent encoder: L0 + L1 software-pipelined ----------------
__global__ void __launch_bounds__(NTHR, 1) enc_kernel(
    const float* __restrict__ in_seq,
    const float4* __restrict__ pW0x, const float4* __restrict__ pW0h,
    const float4* __restrict__ pW1x, const float4* __restrict__ pW1h,
    const float4* __restrict__ pb0, const float4* __restrict__ pb1,
    const float* __restrict__ zerobuf,
    float* __restrict__ y0, float* __restrict__ h1A, float* __restrict__ h1B,
    float* __restrict__ c0out, float* __restrict__ c1out)
{
    extern __shared__ __align__(16) unsigned char smraw[];
    ulonglong2* W0h = (ulonglong2*)smraw;
    ulonglong2* W1x = W0h + 4 * WSS;
    ulonglong2* W1h = W1x + 4 * WSS;
    ulonglong2* W0x = W1h + 4 * WSS;
    float* hs = (float*)(W0x + 4 * WSS64);

    int tid = threadIdx.x, jl = tid & 3, rh = tid >> 2;
    int j0 = blockIdx.x * 4, j = j0 + jl;
    int idx0 = (rh << 9) + j;
    int idx1 = ((rh + 32) << 9) + j;

    {   // load weight tiles (once); global packed rows are 512 u2 per j
        const ulonglong2* g0h = (const ulonglong2*)pW0h + (size_t)j0 * HH;
        const ulonglong2* g1x = (const ulonglong2*)pW1x + (size_t)j0 * HH;
        const ulonglong2* g1h = (const ulonglong2*)pW1h + (size_t)j0 * HH;
#pragma unroll 2
        for (int i = tid; i < 4 * HH; i += NTHR) {
            int jj = i >> 9, kk = i & 511;
            W0h[jj * WSS + kk] = g0h[i];
            W1x[jj * WSS + kk] = g1x[i];
            W1h[jj * WSS + kk] = g1h[i];
        }
        const ulonglong2* g0x = (const ulonglong2*)pW0x + (size_t)j0 * FF;
#pragma unroll
        for (int i = tid; i < 4 * FF; i += NTHR) {
            int jj = i >> 6, kk = i & 63;
            W0x[jj * WSS64 + kk] = g0x[i];
        }
    }
    float4 b0 = pb0[j], b1 = pb1[j];
    float c0a = 0.f, c0b = 0.f, c1a = 0.f, c1b = 0.f;
    __syncthreads();

    unsigned gen = 0;
    for (int slot = 0; slot <= TT; slot++) {
        bool doL0 = (slot < TT);
        bool doL1 = (slot > 0);
        const float* yprev = (slot == 0) ? zerobuf : (y0 + (size_t)(slot - 1) * BH);

        u64 A[8], Bc[8];
        if (doL0) {
            bias_init(A, b0);
            phase64_single(A, in_seq + (size_t)slot * FF, (long)TT * FF, W0x, hs, tid, jl, rh);
        }
        if (doL1) bias_init(Bc, b1);

        if (doL0 && doL1)
            phase512_dual(A, Bc, yprev, W0h, W1x, hs, tid, jl, rh);
        else if (doL0)
            phase512_single(A, yprev, W0h, hs, tid, jl, rh);
        else
            phase512_single(Bc, yprev, W1x, hs, tid, jl, rh);

        if (doL1) {
            const float* h1p = (slot == 1) ? zerobuf : ((slot & 1) ? h1A : h1B);
            phase512_single(Bc, h1p, W1h, hs, tid, jl, rh);
            float* h1o = (slot & 1) ? h1B : h1A;
            h1o[idx0] = cellfin4(Bc[0], Bc[1], Bc[2], Bc[3], c1a);
            h1o[idx1] = cellfin4(Bc[4], Bc[5], Bc[6], Bc[7], c1b);
        }
        if (doL0) {
            float* yo = y0 + (size_t)slot * BH;
            yo[idx0] = cellfin4(A[0], A[1], A[2], A[3], c0a);
            yo[idx1] = cellfin4(A[4], A[5], A[6], A[7], c0b);
        }

        if (slot < TT) {
            gen++;
            grid_barrier(gen);
        }
    }
    c0out[idx0] = c0a; c0out[idx1] = c0b;
    c1out[idx0] = c1a; c1out[idx1] = c1b;
    // final h1 at slot TT (even) -> h1A
}

// ---------------- persistent decoder ----------------
__global__ void __launch_bounds__(NTHR, 1) dec_kernel(
    const float* __restrict__ in_seq,
    const float4* __restrict__ pWd0x, const float4* __restrict__ pWd0c,
    const float4* __restrict__ pWdh0, const float4* __restrict__ pWdx1,
    const float4* __restrict__ pWdh1,
    const float4* __restrict__ pbD0, const float4* __restrict__ pbD0c,
    const float4* __restrict__ pbD1,
    const float* __restrict__ h0init, const float* __restrict__ h1init,
    const float* __restrict__ c0in, const float* __restrict__ c1in,
    float* __restrict__ h0A, float* __restrict__ h0B, float* __restrict__ h1hist)
{
    extern __shared__ __align__(16) unsigned char smraw[];
    ulonglong2* Wc  = (ulonglong2*)smraw;
    ulonglong2* Wh0 = Wc  + 4 * WSS;
    ulonglong2* Wx1 = Wh0 + 4 * WSS;
    ulonglong2* Wh1 = Wx1 + 4 * WSS;
    ulonglong2* W0x = Wh1 + 4 * WSS;
    float* hs = (float*)(W0x + 4 * WSS64);

    int tid = threadIdx.x, jl = tid & 3, rh = tid >> 2;
    int j0 = blockIdx.x * 4, j = j0 + jl;
    int idx0 = (rh << 9) + j;
    int idx1 = ((rh + 32) << 9) + j;

    {
        const ulonglong2* gc  = (const ulonglong2*)pWd0c + (size_t)j0 * HH;
        const ulonglong2* gh0 = (const ulonglong2*)pWdh0 + (size_t)j0 * HH;
        const ulonglong2* gx1 = (const ulonglong2*)pWdx1 + (size_t)j0 * HH;
        const ulonglong2* gh1 = (const ulonglong2*)pWdh1 + (size_t)j0 * HH;
#pragma unroll 2
        for (int i = tid; i < 4 * HH; i += NTHR) {
            int jj = i >> 9, kk = i & 511;
            Wc[jj * WSS + kk]  = gc[i];
            Wh0[jj * WSS + kk] = gh0[i];
            Wx1[jj * WSS + kk] = gx1[i];
            Wh1[jj * WSS + kk] = gh1[i];
        }
        const ulonglong2* g0x = (const ulonglong2*)pWd0x + (size_t)j0 * FF;
#pragma unroll
        for (int i = tid; i < 4 * FF; i += NTHR) {
            int jj = i >> 6, kk = i & 63;
            W0x[jj * WSS64 + kk] = g0x[i];
        }
    }
    float4 bd0 = pbD0[j], bd0c = pbD0c[j], bd1 = pbD1[j];
    float c0a = c0in[idx0], c0b = c0in[idx1];
    float c1a = c1in[idx0], c1b = c1in[idx1];
    __syncthreads();

    unsigned gen = 0;
    const float* h0prev = h0init;
    const float* h1prev = h1init;

    for (int t = 0; t < FUT; t++) {
        // ---- cell d0 ----
        u64 A[8];
        if (t == 0) {
            bias_init(A, bd0);
            phase64_single(A, in_seq + (size_t)(TT - 1) * FF, (long)TT * FF, W0x, hs, tid, jl, rh);
        } else {
            bias_init(A, bd0c);
            phase512_single(A, h1hist + (size_t)(t - 1) * BH, Wc, hs, tid, jl, rh);
        }
        phase512_single(A, h0prev, Wh0, hs, tid, jl, rh);
        float* h0out = (t & 1) ? h0B : h0A;
        h0out[idx0] = cellfin4(A[0], A[1], A[2], A[3], c0a);
        h0out[idx1] = cellfin4(A[4], A[5], A[6], A[7], c0b);
        gen++; grid_barrier(gen);

        // ---- cell d1 ----
        u64 R[8];
        bias_init(R, bd1);
        phase512_single(R, h0out, Wx1, hs, tid, jl, rh);
        phase512_single(R, h1prev, Wh1, hs, tid, jl, rh);
        float* h1o = h1hist + (size_t)t * BH;
        h1o[idx0] = cellfin4(R[0], R[1], R[2], R[3], c1a);
        h1o[idx1] = cellfin4(R[4], R[5], R[6], R[7], c1b);
        if (t < FUT - 1) {
            gen++; grid_barrier(gen);
        }
        h0prev = h0out;
        h1prev = h1o;
    }
}

// ---------------- setup kernels ----------------
// Pair-packed: entry (j,k2): D[(j*K2+k2)*2+0]={i(k),i(k+1),f(k),f(k+1)}, +1={g..,o..}
__global__ void pack_all_kernel(
    const float* __restrict__ s0, const float* __restrict__ s1,
    const float* __restrict__ s2, const float* __restrict__ s3,
    const float* __restrict__ s4, const float* __restrict__ s5,
    const float* __restrict__ s6, const float* __restrict__ s7,
    float4* __restrict__ d0, float4* __restrict__ d1,
    float4* __restrict__ d2, float4* __restrict__ d3,
    float4* __restrict__ d4, float4* __restrict__ d5,
    float4* __restrict__ d6, float4* __restrict__ d7,
    const float* __restrict__ bi0, const float* __restrict__ bh0,
    const float* __restrict__ bi1, const float* __restrict__ bh1,
    const float* __restrict__ bi2, const float* __restrict__ bh2,
    const float* __restrict__ bi3, const float* __restrict__ bh3,
    float4* __restrict__ pb0, float4* __restrict__ pb1,
    float4* __restrict__ pb2, float4* __restrict__ pb3)
{
    int m = blockIdx.y;
    int idx = blockIdx.x * 256 + threadIdx.x;
    if (m < 8) {
        const float* S; float4* D; int Kin;
        switch (m) {
            case 0: S = s0; D = d0; Kin = FF; break;
            case 1: S = s1; D = d1; Kin = HH; break;
            case 2: S = s2; D = d2; Kin = HH; break;
            case 3: S = s3; D = d3; Kin = HH; break;
            case 4: S = s4; D = d4; Kin = FF; break;
            case 5: S = s5; D = d5; Kin = HH; break;
            case 6: S = s6; D = d6; Kin = HH; break;
            default: S = s7; D = d7; Kin = HH; break;
        }
        int K2 = Kin >> 1;
        if (idx >= HH * K2) return;
        int jj = idx / K2, k2 = idx - jj * K2;
        int k = k2 * 2;
        D[idx * 2 + 0] = make_float4(S[jj * Kin + k], S[jj * Kin + k + 1],
                                     S[(jj + 512) * Kin + k], S[(jj + 512) * Kin + k + 1]);
        D[idx * 2 + 1] = make_float4(S[(jj + 1024) * Kin + k], S[(jj + 1024) * Kin + k + 1],
                                     S[(jj + 1536) * Kin + k], S[(jj + 1536) * Kin + k + 1]);
    } else {
        if (idx >= 4 * HH) return;
        int which = idx >> 9, jj = idx & 511;
        const float* A; const float* Bb; float4* P;
        switch (which) {
            case 0: A = bi0; Bb = bh0; P = pb0; break;
            case 1: A = bi1; Bb = bh1; P = pb1; break;
            case 2: A = bi2; Bb = bh2; P = pb2; break;
            default: A = bi3; Bb = bh3; P = pb3; break;
        }
        P[jj] = make_float4(A[jj] + Bb[jj], A[jj + 512] + Bb[jj + 512],
                            A[jj + 1024] + Bb[jj + 1024], A[jj + 1536] + Bb[jj + 1536]);
    }
}

// W' = Wih0 @ fcW (pair-packed out), b' = b_d0 + Wih0 @ fc_b. Reads RAW inputs.
__global__ void combine_dec0_kernel(
    const float* __restrict__ dWih0, const float* __restrict__ fcW,
    const float* __restrict__ dbih0, const float* __restrict__ dbhh0,
    const float* __restrict__ fcb,
    float4* __restrict__ Pc, float4* __restrict__ pbc)
{
    int idx = blockIdx.x * 256 + threadIdx.x;       // HH * 256 entries
    if (idx >= HH * 256) return;
    int jj = idx >> 8, h = (idx & 255) * 2;
    float si0 = 0, si1 = 0, sf0 = 0, sf1 = 0, sg0 = 0, sg1 = 0, so0 = 0, so1 = 0;
#pragma unroll 4
    for (int n = 0; n < FF; n++) {
        float f0 = fcW[n * HH + h], f1 = fcW[n * HH + h + 1];
        float wi = dWih0[jj * FF + n];
        float wf = dWih0[(jj + 512) * FF + n];
        float wg = dWih0[(jj + 1024) * FF + n];
        float wo = dWih0[(jj + 1536) * FF + n];
        si0 += wi * f0; si1 += wi * f1;
        sf0 += wf * f0; sf1 += wf * f1;
        sg0 += wg * f0; sg1 += wg * f1;
        so0 += wo * f0; so1 += wo * f1;
    }
    Pc[idx * 2 + 0] = make_float4(si0, si1, sf0, sf1);
    Pc[idx * 2 + 1] = make_float4(sg0, sg1, so0, so1);
    if ((idx & 255) == 0) {
        float bi = dbih0[jj] + dbhh0[jj];
        float bf = dbih0[jj + 512] + dbhh0[jj + 512];
        float bg = dbih0[jj + 1024] + dbhh0[jj + 1024];
        float bo = dbih0[jj + 1536] + dbhh0[jj + 1536];
#pragma unroll 4
        for (int n = 0; n < FF; n++) {
            float f = fcb[n];
            bi += dWih0[jj * FF + n] * f;
            bf += dWih0[(jj + 512) * FF + n] * f;
            bg += dWih0[(jj + 1024) * FF + n] * f;
            bo += dWih0[(jj + 1536) * FF + n] * f;
        }
        pbc[jj] = make_float4(bi, bf, bg, bo);
    }
}

__global__ void init_kernel(float* zerobuf) {
    int i = blockIdx.x * 256 + threadIdx.x;
    if (i < BH) zerobuf[i] = 0.f;
    if (i < NBLK * 8) g_flag[i] = 0;
    if (i == 0) g_bgen = 0;
}
__global__ void reset_bar_kernel() {
    int i = threadIdx.x;
    if (i < NBLK * 8) g_flag[i] = 0;
    if (i == 0) g_bgen = 0;
}

__global__ void final_fc_kernel(const float* __restrict__ h1hist, const float* __restrict__ fcW,
                                const float* __restrict__ fcb, float* __restrict__ out) {
    int t = blockIdx.y;
    int l = blockIdx.x * 256 + threadIdx.x;
    int b = l >> 6, n = l & 63;
    const float4* h4 = (const float4*)(h1hist + ((size_t)t * BB + b) * HH);
    const float4* w4 = (const float4*)(fcW + (size_t)n * HH);
    float acc = fcb[n];
#pragma unroll 8
    for (int k = 0; k < HH / 4; k++) {
        float4 a = h4[k], w = w4[k];
        acc += a.x * w.x + a.y * w.y + a.z * w.z + a.w * w.w;
    }
    out[((size_t)b * FUT + t) * FF + n] = acc;
}

// ---------------- host ----------------
extern "C" void kernel_launch(void* const* d_in, const int* in_sizes, int n_in,
                              void* d_out, int out_size) {
    const float* in_seq = (const float*)d_in[0];
    const float* eWih0  = (const float*)d_in[1];
    const float* eWhh0  = (const float*)d_in[2];
    const float* ebih0  = (const float*)d_in[3];
    const float* ebhh0  = (const float*)d_in[4];
    const float* eWih1  = (const float*)d_in[5];
    const float* eWhh1  = (const float*)d_in[6];
    const float* ebih1  = (const float*)d_in[7];
    const float* ebhh1  = (const float*)d_in[8];
    const float* dWih0  = (const float*)d_in[9];
    const float* dWhh0  = (const float*)d_in[10];
    const float* dbih0  = (const float*)d_in[11];
    const float* dbhh0  = (const float*)d_in[12];
    const float* dWih1  = (const float*)d_in[13];
    const float* dWhh1  = (const float*)d_in[14];
    const float* dbih1  = (const float*)d_in[15];
    const float* dbhh1  = (const float*)d_in[16];
    const float* fcW    = (const float*)d_in[17];
    const float* fcb    = (const float*)d_in[18];
    float* out = (float*)d_out;

    static int s_attr_done = 0;
    if (!s_attr_done) {
        cudaFuncSetAttribute(enc_kernel, cudaFuncAttributeMaxDynamicSharedMemorySize, ENC_SMEM);
        cudaFuncSetAttribute(dec_kernel, cudaFuncAttributeMaxDynamicSharedMemorySize, DEC_SMEM);
        s_attr_done = 1;
    }

    float4 *pWeih0, *pWehh0, *pWeih1, *pWehh1, *pWdih0, *pWdhh0, *pWdih1, *pWdhh1, *pWd0c;
    float4 *pbE0, *pbE1, *pbD0, *pbD1, *pbD0c;
    float *y0, *h1hist, *zerobuf, *c0, *c1, *h1A, *h1B, *h0A, *h0B;
    cudaGetSymbolAddress((void**)&y0,      g_y0);
    cudaGetSymbolAddress((void**)&h1hist,  g_h1hist);
    cudaGetSymbolAddress((void**)&zerobuf, g_zero);
    cudaGetSymbolAddress((void**)&c0,      g_c0);
    cudaGetSymbolAddress((void**)&c1,      g_c1);
    cudaGetSymbolAddress((void**)&h1A,     g_h1A);
    cudaGetSymbolAddress((void**)&h1B,     g_h1B);
    cudaGetSymbolAddress((void**)&h0A,     g_h0A);
    cudaGetSymbolAddress((void**)&h0B,     g_h0B);
    cudaGetSymbolAddress((void**)&pWeih0,  g_pW_enc_ih0);
    cudaGetSymbolAddress((void**)&pWehh0,  g_pW_enc_hh0);
    cudaGetSymbolAddress((void**)&pWeih1,  g_pW_enc_ih1);
    cudaGetSymbolAddress((void**)&pWehh1,  g_pW_enc_hh1);
    cudaGetSymbolAddress((void**)&pWdih0,  g_pW_dec_ih0);
    cudaGetSymbolAddress((void**)&pWdhh0,  g_pW_dec_hh0);
    cudaGetSymbolAddress((void**)&pWdih1,  g_pW_dec_ih1);
    cudaGetSymbolAddress((void**)&pWdhh1,  g_pW_dec_hh1);
    cudaGetSymbolAddress((void**)&pWd0c,   g_pW_dec0c);
    cudaGetSymbolAddress((void**)&pbE0,    g_pb_enc0);
    cudaGetSymbolAddress((void**)&pbE1,    g_pb_enc1);
    cudaGetSymbolAddress((void**)&pbD0,    g_pb_dec0);
    cudaGetSymbolAddress((void**)&pbD1,    g_pb_dec1);
    cudaGetSymbolAddress((void**)&pbD0c,   g_pb_dec0c);

    // Launch order: harness issues 2 launches first -> app launches at idx 2..
    // [2] pack, [3] combine, [4] init, [5] enc  => ncu -s 5 -c 1 captures enc.
    {
        dim3 grid(512, 9);
        pack_all_kernel<<<grid, 256>>>(
            eWih0, eWhh0, eWih1, eWhh1, dWih0, dWhh0, dWih1, dWhh1,
            pWeih0, pWehh0, pWeih1, pWehh1, pWdih0, pWdhh0, pWdih1, pWdhh1,
            ebih0, ebhh0, ebih1, ebhh1, dbih0, dbhh0, dbih1, dbhh1,
            pbE0, pbE1, pbD0, pbD1);
    }
    combine_dec0_kernel<<<(HH * 256 + 255) / 256, 256>>>(
        dWih0, fcW, dbih0, dbhh0, fcb, pWd0c, pbD0c);
    init_kernel<<<(BH + 255) / 256, 256>>>(zerobuf);

    enc_kernel<<<NBLK, NTHR, ENC_SMEM>>>(
        in_seq, pWeih0, pWehh0, pWeih1, pWehh1, pbE0, pbE1,
        zerobuf, y0, h1A, h1B, c0, c1);

    reset_bar_kernel<<<1, 1024>>>();

    dec_kernel<<<NBLK, NTHR, DEC_SMEM>>>(
        in_seq, pWdih0, pWd0c, pWdhh0, pWdih1, pWdhh1,
        pbD0, pbD0c, pbD1,
        y0 + (size_t)(TT - 1) * BH,
        h1A,
        c0, c1, h0A, h0B, h1hist);

    {
        dim3 grid(16, FUT);
        final_fc_kernel<<<grid, 256>>>(h1hist, fcW, fcb, out);
    }
}

// round 11
// speedup vs baseline: 1.0027x; 1.0016x over previous
#include <cuda_runtime.h>

// LSTM seq2seq: B=64, T=512, F=64, H=512, FUT=96 — persistent v5.
//  - k-pair f32x2 lanes: weights packed as per-gate (k,k+1) 64-bit pairs, so the
//    FFMA2 activation operand comes straight from LDS (NO broadcast MOVs).
//  - 2 rows per thread, 128 thr/block, weights in smem, c in registers.
//  - float4 staging, double-buffered, 1 sync per 64-k chunk; flag-tree barrier.

#define BB 64
#define TT 512
#define FF 64
#define HH 512
#define FUT 96
#define BH (BB*HH)          // 32768

#define NBLK 128
#define NTHR 128
#define WSS   514           // padded per-j row stride (ulonglong2 units) K=512
#define WSS64 66            // padded row stride for K=64
#define HSP 68              // padded floats per staged activation row
#define HSBUFF (64*HSP)

typedef unsigned long long u64;

// ---------------- device scratch ----------------
__device__ float  g_y0[TT*BB*HH];
__device__ float  g_h1hist[FUT*BB*HH];
__device__ float  g_zero[BH];
__device__ float  g_c0[BH], g_c1[BH];
__device__ float  g_h1A[BH], g_h1B[BH], g_h0A[BH], g_h0B[BH];

// pair-packed weights: entry (j,k2) = 2 float4: {i(k),i(k+1),f(k),f(k+1)} and {g.., o..}
__device__ float4 g_pW_enc_ih0[HH*FF];
__device__ float4 g_pW_enc_hh0[HH*HH];
__device__ float4 g_pW_enc_ih1[HH*HH];
__device__ float4 g_pW_enc_hh1[HH*HH];
__device__ float4 g_pW_dec_ih0[HH*FF];
__device__ float4 g_pW_dec_hh0[HH*HH];
__device__ float4 g_pW_dec_ih1[HH*HH];
__device__ float4 g_pW_dec_hh1[HH*HH];
__device__ float4 g_pW_dec0c[HH*HH];
__device__ float4 g_pb_enc0[HH], g_pb_enc1[HH], g_pb_dec0[HH], g_pb_dec1[HH], g_pb_dec0c[HH];

__device__ unsigned g_bgen;
__device__ unsigned g_flag[NBLK*8];

// ---------------- f32x2 helpers ----------------
__device__ __forceinline__ u64 pack2(float a, float b) {
    u64 r;
    asm("mov.b64 %0, {%1, %2};" : "=l"(r) : "r"(__float_as_uint(a)), "r"(__float_as_uint(b)));
    return r;
}
__device__ __forceinline__ float2 unpack2(u64 v) {
    unsigned int lo, hi;
    asm("mov.b64 {%0, %1}, %2;" : "=r"(lo), "=r"(hi) : "l"(v));
    return make_float2(__uint_as_float(lo), __uint_as_float(hi));
}
__device__ __forceinline__ void ffma2(u64& d, u64 a, u64 b) {
    asm("fma.rn.f32x2 %0, %1, %2, %0;" : "+l"(d) : "l"(a), "l"(b));
}

// ---------------- flag-tree grid barrier ----------------
__device__ __forceinline__ void grid_barrier(unsigned gen) {
    __syncthreads();
    int tid = threadIdx.x;
    if (blockIdx.x == 0) {
        if (tid > 0) {
            unsigned v;
            do {
                asm volatile("ld.acquire.gpu.u32 %0, [%1];" : "=r"(v) : "l"(&g_flag[tid * 8]));
            } while (v < gen);
        }
        __syncthreads();
        if (tid == 0) {
            asm volatile("st.release.gpu.u32 [%0], %1;" :: "l"(&g_bgen), "r"(gen));
        }
    } else {
        if (tid == 0) {
            asm volatile("st.release.gpu.u32 [%0], %1;" :: "l"(&g_flag[blockIdx.x * 8]), "r"(gen));
            unsigned v;
            do {
                asm volatile("ld.acquire.gpu.u32 %0, [%1];" : "=r"(v) : "l"(&g_bgen));
            } while (v < gen);
        }
        __syncthreads();
    }
}

// ---------------- chunk compute over 64 k, 2 rows per thread ----------------
// A[0..3] = row0 gates i,f,g,o (each u64 = 2 k-lanes); A[4..7] = row1.
// w: 2 ulonglong2 per k-pair: [2*k2]={wi2,wf2}, [2*k2+1]={wg2,wo2}.
__device__ __forceinline__ void chunk16(
    u64* __restrict__ A,
    const ulonglong2* __restrict__ w,
    const float* __restrict__ h0, const float* __restrict__ h1)
{
#pragma unroll
    for (int k2 = 0; k2 < 32; k2 += 2) {
        ulonglong2 a = *(const ulonglong2*)(h0 + k2 * 2);   // (k..k+1),(k+2..k+3)
        ulonglong2 b = *(const ulonglong2*)(h1 + k2 * 2);
        ulonglong2 wif0 = w[2 * k2 + 0];
        ulonglong2 wgo0 = w[2 * k2 + 1];
        ulonglong2 wif1 = w[2 * k2 + 2];
        ulonglong2 wgo1 = w[2 * k2 + 3];
        ffma2(A[0], a.x, wif0.x); ffma2(A[1], a.x, wif0.y);
        ffma2(A[2], a.x, wgo0.x); ffma2(A[3], a.x, wgo0.y);
        ffma2(A[4], b.x, wif0.x); ffma2(A[5], b.x, wif0.y);
        ffma2(A[6], b.x, wgo0.x); ffma2(A[7], b.x, wgo0.y);
        ffma2(A[0], a.y, wif1.x); ffma2(A[1], a.y, wif1.y);
        ffma2(A[2], a.y, wgo1.x); ffma2(A[3], a.y, wgo1.y);
        ffma2(A[4], b.y, wif1.x); ffma2(A[5], b.y, wif1.y);
        ffma2(A[6], b.y, wgo1.x); ffma2(A[7], b.y, wgo1.y);
    }
}

// Dual matrices sharing the same activations.
__device__ __forceinline__ void chunk16_dual(
    u64* __restrict__ A, u64* __restrict__ B,
    const ulonglong2* __restrict__ wa, const ulonglong2* __restrict__ wb,
    const float* __restrict__ h0, const float* __restrict__ h1)
{
#pragma unroll
    for (int k2 = 0; k2 < 32; k2++) {
        u64 a = *(const u64*)(h0 + k2 * 2);
        u64 b = *(const u64*)(h1 + k2 * 2);
        ulonglong2 waif = wa[2 * k2], wago = wa[2 * k2 + 1];
        ulonglong2 wbif = wb[2 * k2], wbgo = wb[2 * k2 + 1];
        ffma2(A[0], a, waif.x); ffma2(A[1], a, waif.y);
        ffma2(A[2], a, wago.x); ffma2(A[3], a, wago.y);
        ffma2(A[4], b, waif.x); ffma2(A[5], b, waif.y);
        ffma2(A[6], b, wago.x); ffma2(A[7], b, wago.y);
        ffma2(B[0], a, wbif.x); ffma2(B[1], a, wbif.y);
        ffma2(B[2], a, wbgo.x); ffma2(B[3], a, wbgo.y);
        ffma2(B[4], b, wbif.x); ffma2(B[5], b, wbif.y);
        ffma2(B[6], b, wbgo.x); ffma2(B[7], b, wbgo.y);
    }
}

// ---------------- staged phases ----------------
__device__ __forceinline__ void phase512_single(
    u64* __restrict__ A,
    const float* __restrict__ x, const ulonglong2* __restrict__ W,
    float* hs, int tid, int jl, int rh)
{
    const float4* x4 = (const float4*)x;
    int rbase = tid >> 4, c4 = tid & 15;
    float4 pf[8];
#pragma unroll
    for (int u = 0; u < 8; u++) pf[u] = x4[(rbase + u * 8) * 128 + c4];
#pragma unroll 1
    for (int kc = 0; kc < HH; kc += 64) {
        float* buf = hs + ((kc >> 6) & 1) * HSBUFF;
        float4* buf4 = (float4*)buf;
#pragma unroll
        for (int u = 0; u < 8; u++) buf4[(rbase + u * 8) * 17 + c4] = pf[u];
        __syncthreads();
        if (kc + 64 < HH) {
            int k4 = (kc + 64) >> 2;
#pragma unroll
            for (int u = 0; u < 8; u++) pf[u] = x4[(rbase + u * 8) * 128 + k4 + c4];
        }
        chunk16(A, W + jl * WSS + kc, buf + rh * HSP, buf + (rh + 32) * HSP);
    }
}

__device__ __forceinline__ void phase512_dual(
    u64* __restrict__ A, u64* __restrict__ B,
    const float* __restrict__ x,
    const ulonglong2* __restrict__ Wa, const ulonglong2* __restrict__ Wb,
    float* hs, int tid, int jl, int rh)
{
    const float4* x4 = (const float4*)x;
    int rbase = tid >> 4, c4 = tid & 15;
    float4 pf[8];
#pragma unroll
    for (int u = 0; u < 8; u++) pf[u] = x4[(rbase + u * 8) * 128 + c4];
#pragma unroll 1
    for (int kc = 0; kc < HH; kc += 64) {
        float* buf = hs + ((kc >> 6) & 1) * HSBUFF;
        float4* buf4 = (float4*)buf;
#pragma unroll
        for (int u = 0; u < 8; u++) buf4[(rbase + u * 8) * 17 + c4] = pf[u];
        __syncthreads();
        if (kc + 64 < HH) {
            int k4 = (kc + 64) >> 2;
#pragma unroll
            for (int u = 0; u < 8; u++) pf[u] = x4[(rbase + u * 8) * 128 + k4 + c4];
        }
        chunk16_dual(A, B, Wa + jl * WSS + kc, Wb + jl * WSS + kc,
                     buf + rh * HSP, buf + (rh + 32) * HSP);
    }
}

__device__ __forceinline__ void phase64_single(
    u64* __restrict__ A,
    const float* __restrict__ x, long xstride,
    const ulonglong2* __restrict__ W, float* hs, int tid, int jl, int rh)
{
    const float4* x4 = (const float4*)x;
    long xs4 = xstride >> 2;
    int rbase = tid >> 4, c4 = tid & 15;
    float* buf = hs + HSBUFF;   // buffer 1 (parity-safe vs phase512 start)
    float4* buf4 = (float4*)buf;
#pragma unroll
    for (int u = 0; u < 8; u++)
        buf4[(rbase + u * 8) * 17 + c4] = x4[(long)(rbase + u * 8) * xs4 + c4];
    __syncthreads();
    chunk16(A, W + jl * WSS64, buf + rh * HSP, buf + (rh + 32) * HSP);
}

__device__ __forceinline__ float cellfin4(u64 gi2, u64 gf2, u64 gg2, u64 go2, float& c) {
    float2 vi = unpack2(gi2), vf = unpack2(gf2), vg = unpack2(gg2), vo = unpack2(go2);
    float gi = vi.x + vi.y, gf = vf.x + vf.y, gg = vg.x + vg.y, go = vo.x + vo.y;
    float si = 1.f / (1.f + __expf(-gi));
    float sf = 1.f / (1.f + __expf(-gf));
    float so = 1.f / (1.f + __expf(-go));
    float cn = sf * c + si * tanhf(gg);
    c = cn;
    return so * tanhf(cn);
}

__device__ __forceinline__ void bias_init(u64* A, float4 b) {
    A[0] = pack2(b.x, 0.f); A[1] = pack2(b.y, 0.f);
    A[2] = pack2(b.z, 0.f); A[3] = pack2(b.w, 0.f);
    A[4] = A[0]; A[5] = A[1]; A[6] = A[2]; A[7] = A[3];
}

#define ENC_SMEM ((3*4*WSS + 4*WSS64) * 16 + 2*HSBUFF*4)
#define DEC_SMEM ((4*4*WSS + 4*WSS64) * 16 + 2*HSBUFF*4)

// ---------------- persistent encoder: L0 + L1 software-pipelined ----------------
__global__ void __launch_bounds__(NTHR, 1) enc_kernel(
    const float* __restrict__ in_seq,
    const float4* __restrict__ pW0x, const float4* __restrict__ pW0h,
    const float4* __restrict__ pW1x, const float4* __restrict__ pW1h,
    const float4* __restrict__ pb0, const float4* __restrict__ pb1,
    const float* __restrict__ zerobuf,
    float* __restrict__ y0, float* __restrict__ h1A, float* __restrict__ h1B,
    float* __restrict__ c0out, float* __restrict__ c1out)
{
    extern __shared__ __align__(16) unsigned char smraw[];
    ulonglong2* W0h = (ulonglong2*)smraw;
    ulonglong2* W1x = W0h + 4 * WSS;
    ulonglong2* W1h = W1x + 4 * WSS;
    ulonglong2* W0x = W1h + 4 * WSS;
    float* hs = (float*)(W0x + 4 * WSS64);

    int tid = threadIdx.x, jl = tid & 3, rh = tid >> 2;
    int j0 = blockIdx.x * 4, j = j0 + jl;
    int idx0 = (rh << 9) + j;
    int idx1 = ((rh + 32) << 9) + j;

    {   // load weight tiles (once); global packed rows are 512 u2 per j
        const ulonglong2* g0h = (const ulonglong2*)pW0h + (size_t)j0 * HH;
        const ulonglong2* g1x = (const ulonglong2*)pW1x + (size_t)j0 * HH;
        const ulonglong2* g1h = (const ulonglong2*)pW1h + (size_t)j0 * HH;
#pragma unroll 2
        for (int i = tid; i < 4 * HH; i += NTHR) {
            int jj = i >> 9, kk = i & 511;
            W0h[jj * WSS + kk] = g0h[i];
            W1x[jj * WSS + kk] = g1x[i];
            W1h[jj * WSS + kk] = g1h[i];
        }
        const ulonglong2* g0x = (const ulonglong2*)pW0x + (size_t)j0 * FF;
#pragma unroll
        for (int i = tid; i < 4 * FF; i += NTHR) {
            int jj = i >> 6, kk = i & 63;
            W0x[jj * WSS64 + kk] = g0x[i];
        }
    }
    float4 b0 = pb0[j], b1 = pb1[j];
    float c0a = 0.f, c0b = 0.f, c1a = 0.f, c1b = 0.f;
    __syncthreads();

    unsigned gen = 0;
    for (int slot = 0; slot <= TT; slot++) {
        bool doL0 = (slot < TT);
        bool doL1 = (slot > 0);
        const float* yprev = (slot == 0) ? zerobuf : (y0 + (size_t)(slot - 1) * BH);

        u64 A[8], Bc[8];
        if (doL0) {
            bias_init(A, b0);
            phase64_single(A, in_seq + (size_t)slot * FF, (long)TT * FF, W0x, hs, tid, jl, rh);
        }
        if (doL1) bias_init(Bc, b1);

        if (doL0 && doL1)
            phase512_dual(A, Bc, yprev, W0h, W1x, hs, tid, jl, rh);
        else if (doL0)
            phase512_single(A, yprev, W0h, hs, tid, jl, rh);
        else
            phase512_single(Bc, yprev, W1x, hs, tid, jl, rh);

        if (doL1) {
            const float* h1p = (slot == 1) ? zerobuf : ((slot & 1) ? h1A : h1B);
            phase512_single(Bc, h1p, W1h, hs, tid, jl, rh);
            float* h1o = (slot & 1) ? h1B : h1A;
            h1o[idx0] = cellfin4(Bc[0], Bc[1], Bc[2], Bc[3], c1a);
            h1o[idx1] = cellfin4(Bc[4], Bc[5], Bc[6], Bc[7], c1b);
        }
        if (doL0) {
            float* yo = y0 + (size_t)slot * BH;
            yo[idx0] = cellfin4(A[0], A[1], A[2], A[3], c0a);
            yo[idx1] = cellfin4(A[4], A[5], A[6], A[7], c0b);
        }

        if (slot < TT) {
            gen++;
            grid_barrier(gen);
        }
    }
    c0out[idx0] = c0a; c0out[idx1] = c0b;
    c1out[idx0] = c1a; c1out[idx1] = c1b;
    // final h1 at slot TT (even) -> h1A
}

// ---------------- persistent decoder ----------------
__global__ void __launch_bounds__(NTHR, 1) dec_kernel(
    const float* __restrict__ in_seq,
    const float4* __restrict__ pWd0x, const float4* __restrict__ pWd0c,
    const float4* __restrict__ pWdh0, const float4* __restrict__ pWdx1,
    const float4* __restrict__ pWdh1,
    const float4* __restrict__ pbD0, const float4* __restrict__ pbD0c,
    const float4* __restrict__ pbD1,
    const float* __restrict__ h0init, const float* __restrict__ h1init,
    const float* __restrict__ c0in, const float* __restrict__ c1in,
    float* __restrict__ h0A, float* __restrict__ h0B, float* __restrict__ h1hist)
{
    extern __shared__ __align__(16) unsigned char smraw[];
    ulonglong2* Wc  = (ulonglong2*)smraw;
    ulonglong2* Wh0 = Wc  + 4 * WSS;
    ulonglong2* Wx1 = Wh0 + 4 * WSS;
    ulonglong2* Wh1 = Wx1 + 4 * WSS;
    ulonglong2* W0x = Wh1 + 4 * WSS;
    float* hs = (float*)(W0x + 4 * WSS64);

    int tid = threadIdx.x, jl = tid & 3, rh = tid >> 2;
    int j0 = blockIdx.x * 4, j = j0 + jl;
    int idx0 = (rh << 9) + j;
    int idx1 = ((rh + 32) << 9) + j;

    {
        const ulonglong2* gc  = (const ulonglong2*)pWd0c + (size_t)j0 * HH;
        const ulonglong2* gh0 = (const ulonglong2*)pWdh0 + (size_t)j0 * HH;
        const ulonglong2* gx1 = (const ulonglong2*)pWdx1 + (size_t)j0 * HH;
        const ulonglong2* gh1 = (const ulonglong2*)pWdh1 + (size_t)j0 * HH;
#pragma unroll 2
        for (int i = tid; i < 4 * HH; i += NTHR) {
            int jj = i >> 9, kk = i & 511;
            Wc[jj * WSS + kk]  = gc[i];
            Wh0[jj * WSS + kk] = gh0[i];
            Wx1[jj * WSS + kk] = gx1[i];
            Wh1[jj * WSS + kk] = gh1[i];
        }
        const ulonglong2* g0x = (const ulonglong2*)pWd0x + (size_t)j0 * FF;
#pragma unroll
        for (int i = tid; i < 4 * FF; i += NTHR) {
            int jj = i >> 6, kk = i & 63;
            W0x[jj * WSS64 + kk] = g0x[i];
        }
    }
    float4 bd0 = pbD0[j], bd0c = pbD0c[j], bd1 = pbD1[j];
    float c0a = c0in[idx0], c0b = c0in[idx1];
    float c1a = c1in[idx0], c1b = c1in[idx1];
    __syncthreads();

    unsigned gen = 0;
    const float* h0prev = h0init;
    const float* h1prev = h1init;

    for (int t = 0; t < FUT; t++) {
        // ---- cell d0 ----
        u64 A[8];
        if (t == 0) {
            bias_init(A, bd0);
            phase64_single(A, in_seq + (size_t)(TT - 1) * FF, (long)TT * FF, W0x, hs, tid, jl, rh);
        } else {
            bias_init(A, bd0c);
            phase512_single(A, h1hist + (size_t)(t - 1) * BH, Wc, hs, tid, jl, rh);
        }
        phase512_single(A, h0prev, Wh0, hs, tid, jl, rh);
        float* h0out = (t & 1) ? h0B : h0A;
        h0out[idx0] = cellfin4(A[0], A[1], A[2], A[3], c0a);
        h0out[idx1] = cellfin4(A[4], A[5], A[6], A[7], c0b);
        gen++; grid_barrier(gen);

        // ---- cell d1 ----
        u64 R[8];
        bias_init(R, bd1);
        phase512_single(R, h0out, Wx1, hs, tid, jl, rh);
        phase512_single(R, h1prev, Wh1, hs, tid, jl, rh);
        float* h1o = h1hist + (size_t)t * BH;
        h1o[idx0] = cellfin4(R[0], R[1], R[2], R[3], c1a);
        h1o[idx1] = cellfin4(R[4], R[5], R[6], R[7], c1b);
        if (t < FUT - 1) {
            gen++; grid_barrier(gen);
        }
        h0prev = h0out;
        h1prev = h1o;
    }
}

// ---------------- setup kernels ----------------
// Pair-packed: entry (j,k2): D[(j*K2+k2)*2+0]={i(k),i(k+1),f(k),f(k+1)}, +1={g..,o..}
__global__ void pack_all_kernel(
    const float* __restrict__ s0, const float* __restrict__ s1,
    const float* __restrict__ s2, const float* __restrict__ s3,
    const float* __restrict__ s4, const float* __restrict__ s5,
    const float* __restrict__ s6, const float* __restrict__ s7,
    float4* __restrict__ d0, float4* __restrict__ d1,
    float4* __restrict__ d2, float4* __restrict__ d3,
    float4* __restrict__ d4, float4* __restrict__ d5,
    float4* __restrict__ d6, float4* __restrict__ d7,
    const float* __restrict__ bi0, const float* __restrict__ bh0,
    const float* __restrict__ bi1, const float* __restrict__ bh1,
    const float* __restrict__ bi2, const float* __restrict__ bh2,
    const float* __restrict__ bi3, const float* __restrict__ bh3,
    float4* __restrict__ pb0, float4* __restrict__ pb1,
    float4* __restrict__ pb2, float4* __restrict__ pb3)
{
    int m = blockIdx.y;
    int idx = blockIdx.x * 256 + threadIdx.x;
    if (m < 8) {
        const float* S; float4* D; int Kin;
        switch (m) {
            case 0: S = s0; D = d0; Kin = FF; break;
            case 1: S = s1; D = d1; Kin = HH; break;
            case 2: S = s2; D = d2; Kin = HH; break;
            case 3: S = s3; D = d3; Kin = HH; break;
            case 4: S = s4; D = d4; Kin = FF; break;
            case 5: S = s5; D = d5; Kin = HH; break;
            case 6: S = s6; D = d6; Kin = HH; break;
            default: S = s7; D = d7; Kin = HH; break;
        }
        int K2 = Kin >> 1;
        if (idx >= HH * K2) return;
        int jj = idx / K2, k2 = idx - jj * K2;
        int k = k2 * 2;
        D[idx * 2 + 0] = make_float4(S[jj * Kin + k], S[jj * Kin + k + 1],
                                     S[(jj + 512) * Kin + k], S[(jj + 512) * Kin + k + 1]);
        D[idx * 2 + 1] = make_float4(S[(jj + 1024) * Kin + k], S[(jj + 1024) * Kin + k + 1],
                                     S[(jj + 1536) * Kin + k], S[(jj + 1536) * Kin + k + 1]);
    } else {
        if (idx >= 4 * HH) return;
        int which = idx >> 9, jj = idx & 511;
        const float* A; const float* Bb; float4* P;
        switch (which) {
            case 0: A = bi0; Bb = bh0; P = pb0; break;
            case 1: A = bi1; Bb = bh1; P = pb1; break;
            case 2: A = bi2; Bb = bh2; P = pb2; break;
            default: A = bi3; Bb = bh3; P = pb3; break;
        }
        P[jj] = make_float4(A[jj] + Bb[jj], A[jj + 512] + Bb[jj + 512],
                            A[jj + 1024] + Bb[jj + 1024], A[jj + 1536] + Bb[jj + 1536]);
    }
}

// W' = Wih0 @ fcW (pair-packed out), b' = b_d0 + Wih0 @ fc_b. Reads RAW inputs.
__global__ void combine_dec0_kernel(
    const float* __restrict__ dWih0, const float* __restrict__ fcW,
    const float* __restrict__ dbih0, const float* __restrict__ dbhh0,
    const float* __restrict__ fcb,
    float4* __restrict__ Pc, float4* __restrict__ pbc)
{
    int idx = blockIdx.x * 256 + threadIdx.x;       // HH * 256 entries
    if (idx >= HH * 256) return;
    int jj = idx >> 8, h = (idx & 255) * 2;
    float si0 = 0, si1 = 0, sf0 = 0, sf1 = 0, sg0 = 0, sg1 = 0, so0 = 0, so1 = 0;
#pragma unroll 4
    for (int n = 0; n < FF; n++) {
        float f0 = fcW[n * HH + h], f1 = fcW[n * HH + h + 1];
        float wi = dWih0[jj * FF + n];
        float wf = dWih0[(jj + 512) * FF + n];
        float wg = dWih0[(jj + 1024) * FF + n];
        float wo = dWih0[(jj + 1536) * FF + n];
        si0 += wi * f0; si1 += wi * f1;
        sf0 += wf * f0; sf1 += wf * f1;
        sg0 += wg * f0; sg1 += wg * f1;
        so0 += wo * f0; so1 += wo * f1;
    }
    Pc[idx * 2 + 0] = make_float4(si0, si1, sf0, sf1);
    Pc[idx * 2 + 1] = make_float4(sg0, sg1, so0, so1);
    if ((idx & 255) == 0) {
        float bi = dbih0[jj] + dbhh0[jj];
        float bf = dbih0[jj + 512] + dbhh0[jj + 512];
        float bg = dbih0[jj + 1024] + dbhh0[jj + 1024];
        float bo = dbih0[jj + 1536] + dbhh0[jj + 1536];
#pragma unroll 4
        for (int n = 0; n < FF; n++) {
            float f = fcb[n];
            bi += dWih0[jj * FF + n] * f;
            bf += dWih0[(jj + 512) * FF + n] * f;
            bg += dWih0[(jj + 1024) * FF + n] * f;
            bo += dWih0[(jj + 1536) * FF + n] * f;
        }
        pbc[jj] = make_float4(bi, bf, bg, bo);
    }
}

__global__ void init_kernel(float* zerobuf) {
    int i = blockIdx.x * 256 + threadIdx.x;
    if (i < BH) zerobuf[i] = 0.f;
    if (i < NBLK * 8) g_flag[i] = 0;
    if (i == 0) g_bgen = 0;
}
__global__ void reset_bar_kernel() {
    int i = threadIdx.x;
    if (i < NBLK * 8) g_flag[i] = 0;
    if (i == 0) g_bgen = 0;
}

__global__ void final_fc_kernel(const float* __restrict__ h1hist, const float* __restrict__ fcW,
                                const float* __restrict__ fcb, float* __restrict__ out) {
    int t = blockIdx.y;
    int l = blockIdx.x * 256 + threadIdx.x;
    int b = l >> 6, n = l & 63;
    const float4* h4 = (const float4*)(h1hist + ((size_t)t * BB + b) * HH);
    const float4* w4 = (const float4*)(fcW + (size_t)n * HH);
    float acc = fcb[n];
#pragma unroll 8
    for (int k = 0; k < HH / 4; k++) {
        float4 a = h4[k], w = w4[k];
        acc += a.x * w.x + a.y * w.y + a.z * w.z + a.w * w.w;
    }
    out[((size_t)b * FUT + t) * FF + n] = acc;
}

// ---------------- host ----------------
extern "C" void kernel_launch(void* const* d_in, const int* in_sizes, int n_in,
                              void* d_out, int out_size) {
    const float* in_seq = (const float*)d_in[0];
    const float* eWih0  = (const float*)d_in[1];
    const float* eWhh0  = (const float*)d_in[2];
    const float* ebih0  = (const float*)d_in[3];
    const float* ebhh0  = (const float*)d_in[4];
    const float* eWih1  = (const float*)d_in[5];
    const float* eWhh1  = (const float*)d_in[6];
    const float* ebih1  = (const float*)d_in[7];
    const float* ebhh1  = (const float*)d_in[8];
    const float* dWih0  = (const float*)d_in[9];
    const float* dWhh0  = (const float*)d_in[10];
    const float* dbih0  = (const float*)d_in[11];
    const float* dbhh0  = (const float*)d_in[12];
    const float* dWih1  = (const float*)d_in[13];
    const float* dWhh1  = (const float*)d_in[14];
    const float* dbih1  = (const float*)d_in[15];
    const float* dbhh1  = (const float*)d_in[16];
    const float* fcW    = (const float*)d_in[17];
    const float* fcb    = (const float*)d_in[18];
    float* out = (float*)d_out;

    static int s_attr_done = 0;
    if (!s_attr_done) {
        cudaFuncSetAttribute(enc_kernel, cudaFuncAttributeMaxDynamicSharedMemorySize, ENC_SMEM);
        cudaFuncSetAttribute(dec_kernel, cudaFuncAttributeMaxDynamicSharedMemorySize, DEC_SMEM);
        s_attr_done = 1;
    }

    float4 *pWeih0, *pWehh0, *pWeih1, *pWehh1, *pWdih0, *pWdhh0, *pWdih1, *pWdhh1, *pWd0c;
    float4 *pbE0, *pbE1, *pbD0, *pbD1, *pbD0c;
    float *y0, *h1hist, *zerobuf, *c0, *c1, *h1A, *h1B, *h0A, *h0B;
    cudaGetSymbolAddress((void**)&y0,      g_y0);
    cudaGetSymbolAddress((void**)&h1hist,  g_h1hist);
    cudaGetSymbolAddress((void**)&zerobuf, g_zero);
    cudaGetSymbolAddress((void**)&c0,      g_c0);
    cudaGetSymbolAddress((void**)&c1,      g_c1);
    cudaGetSymbolAddress((void**)&h1A,     g_h1A);
    cudaGetSymbolAddress((void**)&h1B,     g_h1B);
    cudaGetSymbolAddress((void**)&h0A,     g_h0A);
    cudaGetSymbolAddress((void**)&h0B,     g_h0B);
    cudaGetSymbolAddress((void**)&pWeih0,  g_pW_enc_ih0);
    cudaGetSymbolAddress((void**)&pWehh0,  g_pW_enc_hh0);
    cudaGetSymbolAddress((void**)&pWeih1,  g_pW_enc_ih1);
    cudaGetSymbolAddress((void**)&pWehh1,  g_pW_enc_hh1);
    cudaGetSymbolAddress((void**)&pWdih0,  g_pW_dec_ih0);
    cudaGetSymbolAddress((void**)&pWdhh0,  g_pW_dec_hh0);
    cudaGetSymbolAddress((void**)&pWdih1,  g_pW_dec_ih1);
    cudaGetSymbolAddress((void**)&pWdhh1,  g_pW_dec_hh1);
    cudaGetSymbolAddress((void**)&pWd0c,   g_pW_dec0c);
    cudaGetSymbolAddress((void**)&pbE0,    g_pb_enc0);
    cudaGetSymbolAddress((void**)&pbE1,    g_pb_enc1);
    cudaGetSymbolAddress((void**)&pbD0,    g_pb_dec0);
    cudaGetSymbolAddress((void**)&pbD1,    g_pb_dec1);
    cudaGetSymbolAddress((void**)&pbD0c,   g_pb_dec0c);

    // Launch order: harness issues 2 launches first -> app launches at idx 2..
    // [2] pack, [3] combine, [4] init, [5] enc  => ncu -s 5 -c 1 captures enc.
    {
        dim3 grid(512, 9);
        pack_all_kernel<<<grid, 256>>>(
            eWih0, eWhh0, eWih1, eWhh1, dWih0, dWhh0, dWih1, dWhh1,
            pWeih0, pWehh0, pWeih1, pWehh1, pWdih0, pWdhh0, pWdih1, pWdhh1,
            ebih0, ebhh0, ebih1, ebhh1, dbih0, dbhh0, dbih1, dbhh1,
            pbE0, pbE1, pbD0, pbD1);
    }
    combine_dec0_kernel<<<(HH * 256 + 255) / 256, 256>>>(
        dWih0, fcW, dbih0, dbhh0, fcb, pWd0c, pbD0c);
    init_kernel<<<(BH + 255) / 256, 256>>>(zerobuf);

    enc_kernel<<<NBLK, NTHR, ENC_SMEM>>>(
        in_seq, pWeih0, pWehh0, pWeih1, pWehh1, pbE0, pbE1,
        zerobuf, y0, h1A, h1B, c0, c1);

    reset_bar_kernel<<<1, 1024>>>();

    dec_kernel<<<NBLK, NTHR, DEC_SMEM>>>(
        in_seq, pWdih0, pWd0c, pWdhh0, pWdih1, pWdhh1,
        pbD0, pbD0c, pbD1,
        y0 + (size_t)(TT - 1) * BH,
        h1A,
        c0, c1, h0A, h0B, h1hist);

    {
        dim3 grid(16, FUT);
        final_fc_kernel<<<grid, 256>>>(h1hist, fcW, fcb, out);
    }
}